// round 3
// baseline (speedup 1.0000x reference)
#include <cuda_runtime.h>
#include <cuda_bf16.h>
#include <cstdint>

// Problem constants
#define F_IN 256
#define H1   128
#define H2   64
#define MAXN 100000

// Scratch (allocation-free rule: __device__ globals). 256B aligned for float4 / red.v4.
__device__ __align__(256) float g_dinv[MAXN];             // deg, then rsqrt(deg)
__device__ __align__(256) float g_h[(size_t)MAXN * H1];   // h1, then hidden
__device__ __align__(256) float g_agg[(size_t)MAXN * H1]; // agg1, then agg2
__device__ int g_is64;                                    // edge_index dtype flag

// ---------------------------------------------------------------------------
// Detect edge_index dtype: int64 little-endian with values < 2^31 has ALL odd
// int32 words == 0. Scan first 512 words (256 edges worth). Deterministic.
__global__ void k_detect(const int* __restrict__ ei32, int words) {
    __shared__ int anynz;
    if (threadIdx.x == 0) anynz = 0;
    __syncthreads();
    int idx = 1 + 2 * (int)threadIdx.x;   // odd words 1,3,...,511
    if (idx < words && ei32[idx] != 0) atomicExch(&anynz, 1);
    __syncthreads();
    if (threadIdx.x == 0) g_is64 = (anynz == 0) ? 1 : 0;
}

__device__ __forceinline__ int edge_at(const void* ei, size_t idx) {
    if (g_is64) return (int)((const long long*)ei)[idx];
    return ((const int*)ei)[idx];
}

// ---------------------------------------------------------------------------
__global__ void k_deg_init(float* deg, int n) {
    int i = blockIdx.x * blockDim.x + threadIdx.x;
    if (i < n) deg[i] = 1.0f;
}

__global__ void k_deg_count(const void* __restrict__ ei, float* deg, int E, int M) {
    int e = blockIdx.x * blockDim.x + threadIdx.x;
    if (e < E) {
        int d = edge_at(ei, (size_t)E + e);
        if ((unsigned)d < (unsigned)M) atomicAdd(deg + d, 1.0f);
    }
}

__global__ void k_rsqrt(float* deg, int n) {
    int i = blockIdx.x * blockDim.x + threadIdx.x;
    if (i < n) deg[i] = rsqrtf(deg[i]);
}

// ---------------------------------------------------------------------------
// GEMM1: H[M,128] = A[M,256] @ B[256,128];  AGG = H * dinv^2 (self-loop term)
__global__ __launch_bounds__(256) void k_gemm1(
    const float* __restrict__ A, const float* __restrict__ B,
    const float* __restrict__ dinv,
    float* __restrict__ H, float* __restrict__ AGG, int M)
{
    const int K = F_IN;
    __shared__ float As[8][128];
    __shared__ float Bs[8][128];
    int block_row = blockIdx.x * 128;
    int tid = threadIdx.x;
    int tr = tid / 16;
    int tc = tid % 16;

    int a_row = tid >> 1;
    int a_col = (tid & 1) * 4;
    int b_row = tid >> 5;
    int b_col = (tid & 31) * 4;

    float acc[8][8];
#pragma unroll
    for (int i = 0; i < 8; i++)
#pragma unroll
        for (int j = 0; j < 8; j++) acc[i][j] = 0.0f;

    for (int k0 = 0; k0 < K; k0 += 8) {
        float4 av = make_float4(0.f, 0.f, 0.f, 0.f);
        int gr = block_row + a_row;
        if (gr < M) av = *(const float4*)(A + (size_t)gr * K + k0 + a_col);
        As[a_col + 0][a_row] = av.x;
        As[a_col + 1][a_row] = av.y;
        As[a_col + 2][a_row] = av.z;
        As[a_col + 3][a_row] = av.w;
        float4 bv = *(const float4*)(B + (size_t)(k0 + b_row) * 128 + b_col);
        *(float4*)&Bs[b_row][b_col] = bv;
        __syncthreads();
#pragma unroll
        for (int k = 0; k < 8; k++) {
            float ar[8], br[8];
#pragma unroll
            for (int i = 0; i < 8; i++) ar[i] = As[k][tr * 8 + i];
#pragma unroll
            for (int j = 0; j < 8; j++) br[j] = Bs[k][tc * 8 + j];
#pragma unroll
            for (int i = 0; i < 8; i++)
#pragma unroll
                for (int j = 0; j < 8; j++) acc[i][j] += ar[i] * br[j];
        }
        __syncthreads();
    }
#pragma unroll
    for (int i = 0; i < 8; i++) {
        int gr = block_row + tr * 8 + i;
        if (gr >= M) break;
        float d = dinv[gr];
        float d2 = d * d;
#pragma unroll
        for (int j = 0; j < 8; j += 4) {
            int gc = tc * 8 + j;
            float4 v = make_float4(acc[i][j], acc[i][j+1], acc[i][j+2], acc[i][j+3]);
            *(float4*)(H + (size_t)gr * 128 + gc) = v;
            float4 s = make_float4(v.x * d2, v.y * d2, v.z * d2, v.w * d2);
            *(float4*)(AGG + (size_t)gr * 128 + gc) = s;
        }
    }
}

// ---------------------------------------------------------------------------
// Edge scatter: one warp per edge. AGG[dst] += dinv[src]*dinv[dst] * H[src]
__global__ __launch_bounds__(256) void k_scatter(
    const void* __restrict__ ei, const float* __restrict__ dinv,
    const float* __restrict__ H, float* __restrict__ AGG, int E, int M)
{
    int w = (blockIdx.x * blockDim.x + threadIdx.x) >> 5;
    int lane = threadIdx.x & 31;
    if (w >= E) return;
    int s = edge_at(ei, (size_t)w);
    int d = edge_at(ei, (size_t)E + w);
    if ((unsigned)s >= (unsigned)M || (unsigned)d >= (unsigned)M) return;
    float coef = dinv[s] * dinv[d];
    float4 v = *(const float4*)(H + (size_t)s * 128 + lane * 4);
    v.x *= coef; v.y *= coef; v.z *= coef; v.w *= coef;
    float* p = AGG + (size_t)d * 128 + lane * 4;
    asm volatile("red.global.add.v4.f32 [%0], {%1, %2, %3, %4};"
                 :: "l"(p), "f"(v.x), "f"(v.y), "f"(v.z), "f"(v.w)
                 : "memory");
}

// ---------------------------------------------------------------------------
// hidden = relu(agg1 + b1);  H = hidden;  AGG = hidden * dinv^2
__global__ void k_hidden(const float* __restrict__ b1, const float* __restrict__ dinv,
                         float* __restrict__ H, float* __restrict__ AGG, int M)
{
    int t = blockIdx.x * blockDim.x + threadIdx.x;
    int total = M * 32;
    if (t >= total) return;
    int row = t >> 5;
    int c4 = (t & 31) * 4;
    float4 a = ((const float4*)AGG)[t];
    a.x = fmaxf(a.x + b1[c4 + 0], 0.f);
    a.y = fmaxf(a.y + b1[c4 + 1], 0.f);
    a.z = fmaxf(a.z + b1[c4 + 2], 0.f);
    a.w = fmaxf(a.w + b1[c4 + 3], 0.f);
    ((float4*)H)[t] = a;
    float d = dinv[row];
    float d2 = d * d;
    float4 s = make_float4(a.x * d2, a.y * d2, a.z * d2, a.w * d2);
    ((float4*)AGG)[t] = s;
}

// ---------------------------------------------------------------------------
// GEMM2: out = AGG[M,128] @ [w2|w3][128,128] + [b2|b3], split mu/logvar write.
__global__ __launch_bounds__(256) void k_gemm2(
    const float* __restrict__ A,
    const float* __restrict__ w2, const float* __restrict__ w3,
    const float* __restrict__ b2, const float* __restrict__ b3,
    float* __restrict__ out, int M)
{
    const int K = H1;
    __shared__ float As[8][128];
    __shared__ float Bs[8][128];
    int block_row = blockIdx.x * 128;
    int tid = threadIdx.x;
    int tr = tid / 16;
    int tc = tid % 16;

    int a_row = tid >> 1;
    int a_col = (tid & 1) * 4;
    int b_row = tid >> 5;
    int b_col = (tid & 31) * 4;

    float acc[8][8];
#pragma unroll
    for (int i = 0; i < 8; i++)
#pragma unroll
        for (int j = 0; j < 8; j++) acc[i][j] = 0.0f;

    for (int k0 = 0; k0 < K; k0 += 8) {
        float4 av = make_float4(0.f, 0.f, 0.f, 0.f);
        int gr = block_row + a_row;
        if (gr < M) av = *(const float4*)(A + (size_t)gr * K + k0 + a_col);
        As[a_col + 0][a_row] = av.x;
        As[a_col + 1][a_row] = av.y;
        As[a_col + 2][a_row] = av.z;
        As[a_col + 3][a_row] = av.w;
        int kk = k0 + b_row;
        float4 bv;
        if (b_col < 64) bv = *(const float4*)(w2 + (size_t)kk * 64 + b_col);
        else            bv = *(const float4*)(w3 + (size_t)kk * 64 + b_col - 64);
        *(float4*)&Bs[b_row][b_col] = bv;
        __syncthreads();
#pragma unroll
        for (int k = 0; k < 8; k++) {
            float ar[8], br[8];
#pragma unroll
            for (int i = 0; i < 8; i++) ar[i] = As[k][tr * 8 + i];
#pragma unroll
            for (int j = 0; j < 8; j++) br[j] = Bs[k][tc * 8 + j];
#pragma unroll
            for (int i = 0; i < 8; i++)
#pragma unroll
                for (int j = 0; j < 8; j++) acc[i][j] += ar[i] * br[j];
        }
        __syncthreads();
    }
    bool is_mu = (tc < 8);
    const float* bias = is_mu ? b2 : b3;
    int cbase = is_mu ? (tc * 8) : (tc * 8 - 64);
    size_t half_off = is_mu ? 0 : (size_t)M * 64;
#pragma unroll
    for (int i = 0; i < 8; i++) {
        int gr = block_row + tr * 8 + i;
        if (gr >= M) break;
#pragma unroll
        for (int j = 0; j < 8; j += 4) {
            float4 v = make_float4(acc[i][j]   + bias[cbase + j],
                                   acc[i][j+1] + bias[cbase + j + 1],
                                   acc[i][j+2] + bias[cbase + j + 2],
                                   acc[i][j+3] + bias[cbase + j + 3]);
            *(float4*)(out + half_off + (size_t)gr * 64 + cbase + j) = v;
        }
    }
}

// ---------------------------------------------------------------------------
extern "C" void kernel_launch(void* const* d_in, const int* in_sizes, int n_in,
                              void* d_out, int out_size)
{
    // Resolve inputs by element count (robust to metadata ordering).
    const float *x = nullptr, *w1 = nullptr, *b1 = nullptr;
    const float *w2 = nullptr, *b2 = nullptr, *w3 = nullptr, *b3 = nullptr;
    const void* ei = nullptr;
    int M = 0, E = 0;

    for (int i = 0; i < n_in; i++) {
        int sz = in_sizes[i];
        if (sz == F_IN * H1) {
            w1 = (const float*)d_in[i];
        } else if (sz == H1) {
            b1 = (const float*)d_in[i];
        } else if (sz == H1 * H2) {
            if (!w2) w2 = (const float*)d_in[i];
            else     w3 = (const float*)d_in[i];
        } else if (sz == H2) {
            if (!b2) b2 = (const float*)d_in[i];
            else     b3 = (const float*)d_in[i];
        } else if (sz < 8000000) {
            ei = d_in[i];           // edge_index: 2*E elements (3.2M)
            E = sz / 2;
        } else {
            x = (const float*)d_in[i];  // N*256 floats (25.6M)
            M = sz / F_IN;
        }
    }

    float *dinv, *H, *AGG;
    cudaGetSymbolAddress((void**)&dinv, g_dinv);
    cudaGetSymbolAddress((void**)&H,    g_h);
    cudaGetSymbolAddress((void**)&AGG,  g_agg);

    float* out = (float*)d_out;

    // dtype detection (int32 vs int64 edge_index)
    k_detect<<<1, 256>>>((const int*)ei, 2 * E);

    // degrees
    k_deg_init<<<(M + 255) / 256, 256>>>(dinv, M);
    k_deg_count<<<(E + 255) / 256, 256>>>(ei, dinv, E, M);
    k_rsqrt<<<(M + 255) / 256, 256>>>(dinv, M);

    int gblocks = (M + 127) / 128;
    k_gemm1<<<gblocks, 256>>>(x, w1, dinv, H, AGG, M);
    int sblocks = (E * 32 + 255) / 256;
    k_scatter<<<sblocks, 256>>>(ei, dinv, H, AGG, E, M);
    k_hidden<<<(M * 32 + 255) / 256, 256>>>(b1, dinv, H, AGG, M);
    k_scatter<<<sblocks, 256>>>(ei, dinv, H, AGG, E, M);
    k_gemm2<<<gblocks, 256>>>(AGG, w2, w3, b2, b3, out, M);
    (void)out_size;
}

// round 4
// speedup vs baseline: 1.5470x; 1.5470x over previous
#include <cuda_runtime.h>
#include <cuda_bf16.h>
#include <cstdint>

#define F_IN 256
#define H1   128
#define H2   64
#define MAXN 100000
#define MAXE 2000000

// Scratch (__device__ globals; allocation-free rule)
__device__ __align__(256) float g_dinv[MAXN];
__device__ __align__(256) float g_h[(size_t)MAXN * H1];    // h1, later agg2
__device__ __align__(256) float g_agg[(size_t)MAXN * H1];  // hidden
__device__ int g_cnt[MAXN];       // per-dst edge count
__device__ int g_incl[MAXN];      // inclusive scan (within block)
__device__ int g_off[MAXN];       // CSR row offsets
__device__ int g_cur[MAXN];       // bump cursors for fill
__device__ int g_bsum[256];       // per-block sums for scan
__device__ int g_esrc[MAXE];      // CSR: src node per slot (grouped by dst)
__device__ int g_is64;            // edge dtype flag

// ---------------------------------------------------------------------------
// edge_index dtype detect: int64 LE with values < 2^31 has all odd words zero.
__global__ void k_detect(const int* __restrict__ ei32, int words) {
    __shared__ int anynz;
    if (threadIdx.x == 0) anynz = 0;
    __syncthreads();
    int idx = 1 + 2 * (int)threadIdx.x;
    if (idx < words && ei32[idx] != 0) atomicExch(&anynz, 1);
    __syncthreads();
    if (threadIdx.x == 0) g_is64 = (anynz == 0) ? 1 : 0;
}

__device__ __forceinline__ int edge_at(const void* ei, size_t idx) {
    if (g_is64) return (int)((const long long*)ei)[idx];
    return ((const int*)ei)[idx];
}

// ---------------------------------------------------------------------------
__global__ void k_zero_cnt(int* cnt, int n) {
    int i = blockIdx.x * blockDim.x + threadIdx.x;
    if (i < n) cnt[i] = 0;
}

__global__ void k_hist(const void* __restrict__ ei, int* cnt, int E, int M) {
    int e = blockIdx.x * blockDim.x + threadIdx.x;
    if (e < E) {
        int d = edge_at(ei, (size_t)E + e);
        if ((unsigned)d < (unsigned)M) atomicAdd(cnt + d, 1);
    }
}

__global__ void k_dinv(const int* __restrict__ cnt, float* dinv, int n) {
    int i = blockIdx.x * blockDim.x + threadIdx.x;
    if (i < n) dinv[i] = rsqrtf(1.0f + (float)cnt[i]);
}

// 3-phase exclusive scan of cnt -> off (and cur = off)
__global__ void k_scan1(const int* __restrict__ cnt, int* incl, int* bsum, int M) {
    __shared__ int sh[1024];
    int i = blockIdx.x * 1024 + threadIdx.x;
    int v = (i < M) ? cnt[i] : 0;
    sh[threadIdx.x] = v;
    __syncthreads();
#pragma unroll
    for (int d = 1; d < 1024; d <<= 1) {
        int t = (threadIdx.x >= d) ? sh[threadIdx.x - d] : 0;
        __syncthreads();
        sh[threadIdx.x] += t;
        __syncthreads();
    }
    if (i < M) incl[i] = sh[threadIdx.x];
    if (threadIdx.x == 1023) bsum[blockIdx.x] = sh[1023];
}

__global__ void k_scan2(int* bsum, int nb) {
    if (threadIdx.x == 0 && blockIdx.x == 0) {
        int acc = 0;
        for (int i = 0; i < nb; i++) { int t = bsum[i]; bsum[i] = acc; acc += t; }
    }
}

__global__ void k_scan3(const int* __restrict__ incl, const int* __restrict__ cnt,
                        const int* __restrict__ bsum, int* off, int* cur, int M) {
    int i = blockIdx.x * blockDim.x + threadIdx.x;
    if (i < M) {
        int o = incl[i] - cnt[i] + bsum[i >> 10];
        off[i] = o;
        cur[i] = o;
    }
}

__global__ void k_fill(const void* __restrict__ ei, int* cur, int* esrc, int E, int M) {
    int e = blockIdx.x * blockDim.x + threadIdx.x;
    if (e < E) {
        int s = edge_at(ei, (size_t)e);
        int d = edge_at(ei, (size_t)E + e);
        if ((unsigned)s < (unsigned)M && (unsigned)d < (unsigned)M) {
            int pos = atomicAdd(cur + d, 1);
            esrc[pos] = s;
        }
    }
}

// ---------------------------------------------------------------------------
// GEMM1: H[M,128] = A[M,256] @ B[256,128] (no epilogue extras now)
__global__ __launch_bounds__(256) void k_gemm1(
    const float* __restrict__ A, const float* __restrict__ B,
    float* __restrict__ H, int M)
{
    const int K = F_IN;
    __shared__ float As[8][128];
    __shared__ float Bs[8][128];
    int block_row = blockIdx.x * 128;
    int tid = threadIdx.x;
    int tr = tid / 16;
    int tc = tid % 16;

    int a_row = tid >> 1;
    int a_col = (tid & 1) * 4;
    int b_row = tid >> 5;
    int b_col = (tid & 31) * 4;

    float acc[8][8];
#pragma unroll
    for (int i = 0; i < 8; i++)
#pragma unroll
        for (int j = 0; j < 8; j++) acc[i][j] = 0.0f;

    for (int k0 = 0; k0 < K; k0 += 8) {
        float4 av = make_float4(0.f, 0.f, 0.f, 0.f);
        int gr = block_row + a_row;
        if (gr < M) av = *(const float4*)(A + (size_t)gr * K + k0 + a_col);
        As[a_col + 0][a_row] = av.x;
        As[a_col + 1][a_row] = av.y;
        As[a_col + 2][a_row] = av.z;
        As[a_col + 3][a_row] = av.w;
        float4 bv = *(const float4*)(B + (size_t)(k0 + b_row) * 128 + b_col);
        *(float4*)&Bs[b_row][b_col] = bv;
        __syncthreads();
#pragma unroll
        for (int k = 0; k < 8; k++) {
            float ar[8], br[8];
#pragma unroll
            for (int i = 0; i < 8; i++) ar[i] = As[k][tr * 8 + i];
#pragma unroll
            for (int j = 0; j < 8; j++) br[j] = Bs[k][tc * 8 + j];
#pragma unroll
            for (int i = 0; i < 8; i++)
#pragma unroll
                for (int j = 0; j < 8; j++) acc[i][j] += ar[i] * br[j];
        }
        __syncthreads();
    }
#pragma unroll
    for (int i = 0; i < 8; i++) {
        int gr = block_row + tr * 8 + i;
        if (gr >= M) break;
#pragma unroll
        for (int j = 0; j < 8; j += 4) {
            float4 v = make_float4(acc[i][j], acc[i][j+1], acc[i][j+2], acc[i][j+3]);
            *(float4*)(H + (size_t)gr * 128 + tc * 8 + j) = v;
        }
    }
}

// ---------------------------------------------------------------------------
// CSR aggregation: one warp per dst node. Register accumulation, single store.
// Hout[d] = sum_{s in N(d)} dinv[s]*dinv[d]*Hin[s] + dinv[d]^2*Hin[d]  (+b, relu)
template<bool RELU>
__global__ __launch_bounds__(256) void k_agg(
    const int* __restrict__ esrc, const int* __restrict__ off,
    const int* __restrict__ cnt, const float* __restrict__ dinv,
    const float* __restrict__ bias,
    const float* __restrict__ Hin, float* __restrict__ Hout, int M)
{
    int node = (blockIdx.x * blockDim.x + threadIdx.x) >> 5;
    int lane = threadIdx.x & 31;
    if (node >= M) return;
    float di = dinv[node];
    float d2 = di * di;
    float4 acc = *(const float4*)(Hin + (size_t)node * 128 + lane * 4);
    acc.x *= d2; acc.y *= d2; acc.z *= d2; acc.w *= d2;

    int o = off[node], c = cnt[node];
    for (int base = 0; base < c; base += 32) {
        int rem = c - base;
        int lim = rem < 32 ? rem : 32;
        int sv = 0; float dv = 0.f;
        if (lane < lim) { sv = esrc[o + base + lane]; dv = dinv[sv]; }
        for (int j = 0; j < lim; j++) {
            int s = __shfl_sync(0xffffffffu, sv, j);
            float ds = __shfl_sync(0xffffffffu, dv, j);
            float coef = ds * di;
            float4 v = *(const float4*)(Hin + (size_t)s * 128 + lane * 4);
            acc.x = fmaf(v.x, coef, acc.x);
            acc.y = fmaf(v.y, coef, acc.y);
            acc.z = fmaf(v.z, coef, acc.z);
            acc.w = fmaf(v.w, coef, acc.w);
        }
    }
    if (RELU) {
        float4 b4 = *(const float4*)(bias + lane * 4);
        acc.x = fmaxf(acc.x + b4.x, 0.f);
        acc.y = fmaxf(acc.y + b4.y, 0.f);
        acc.z = fmaxf(acc.z + b4.z, 0.f);
        acc.w = fmaxf(acc.w + b4.w, 0.f);
    }
    *(float4*)(Hout + (size_t)node * 128 + lane * 4) = acc;
}

// ---------------------------------------------------------------------------
// GEMM2: out = A[M,128] @ [w2|w3][128,128] + [b2|b3], split mu/logvar write.
__global__ __launch_bounds__(256) void k_gemm2(
    const float* __restrict__ A,
    const float* __restrict__ w2, const float* __restrict__ w3,
    const float* __restrict__ b2, const float* __restrict__ b3,
    float* __restrict__ out, int M)
{
    const int K = H1;
    __shared__ float As[8][128];
    __shared__ float Bs[8][128];
    int block_row = blockIdx.x * 128;
    int tid = threadIdx.x;
    int tr = tid / 16;
    int tc = tid % 16;

    int a_row = tid >> 1;
    int a_col = (tid & 1) * 4;
    int b_row = tid >> 5;
    int b_col = (tid & 31) * 4;

    float acc[8][8];
#pragma unroll
    for (int i = 0; i < 8; i++)
#pragma unroll
        for (int j = 0; j < 8; j++) acc[i][j] = 0.0f;

    for (int k0 = 0; k0 < K; k0 += 8) {
        float4 av = make_float4(0.f, 0.f, 0.f, 0.f);
        int gr = block_row + a_row;
        if (gr < M) av = *(const float4*)(A + (size_t)gr * K + k0 + a_col);
        As[a_col + 0][a_row] = av.x;
        As[a_col + 1][a_row] = av.y;
        As[a_col + 2][a_row] = av.z;
        As[a_col + 3][a_row] = av.w;
        int kk = k0 + b_row;
        float4 bv;
        if (b_col < 64) bv = *(const float4*)(w2 + (size_t)kk * 64 + b_col);
        else            bv = *(const float4*)(w3 + (size_t)kk * 64 + b_col - 64);
        *(float4*)&Bs[b_row][b_col] = bv;
        __syncthreads();
#pragma unroll
        for (int k = 0; k < 8; k++) {
            float ar[8], br[8];
#pragma unroll
            for (int i = 0; i < 8; i++) ar[i] = As[k][tr * 8 + i];
#pragma unroll
            for (int j = 0; j < 8; j++) br[j] = Bs[k][tc * 8 + j];
#pragma unroll
            for (int i = 0; i < 8; i++)
#pragma unroll
                for (int j = 0; j < 8; j++) acc[i][j] += ar[i] * br[j];
        }
        __syncthreads();
    }
    bool is_mu = (tc < 8);
    const float* bias = is_mu ? b2 : b3;
    int cbase = is_mu ? (tc * 8) : (tc * 8 - 64);
    size_t half_off = is_mu ? 0 : (size_t)M * 64;
#pragma unroll
    for (int i = 0; i < 8; i++) {
        int gr = block_row + tr * 8 + i;
        if (gr >= M) break;
#pragma unroll
        for (int j = 0; j < 8; j += 4) {
            float4 v = make_float4(acc[i][j]   + bias[cbase + j],
                                   acc[i][j+1] + bias[cbase + j + 1],
                                   acc[i][j+2] + bias[cbase + j + 2],
                                   acc[i][j+3] + bias[cbase + j + 3]);
            *(float4*)(out + half_off + (size_t)gr * 64 + cbase + j) = v;
        }
    }
}

// ---------------------------------------------------------------------------
extern "C" void kernel_launch(void* const* d_in, const int* in_sizes, int n_in,
                              void* d_out, int out_size)
{
    const float *x = nullptr, *w1 = nullptr, *b1 = nullptr;
    const float *w2 = nullptr, *b2 = nullptr, *w3 = nullptr, *b3 = nullptr;
    const void* ei = nullptr;
    int M = 0, E = 0;

    for (int i = 0; i < n_in; i++) {
        int sz = in_sizes[i];
        if (sz == F_IN * H1) {
            w1 = (const float*)d_in[i];
        } else if (sz == H1) {
            b1 = (const float*)d_in[i];
        } else if (sz == H1 * H2) {
            if (!w2) w2 = (const float*)d_in[i];
            else     w3 = (const float*)d_in[i];
        } else if (sz == H2) {
            if (!b2) b2 = (const float*)d_in[i];
            else     b3 = (const float*)d_in[i];
        } else if (sz < 8000000) {
            ei = d_in[i];
            E = sz / 2;
        } else {
            x = (const float*)d_in[i];
            M = sz / F_IN;
        }
    }

    float *dinv, *H, *AGG;
    int *cnt, *incl, *off, *cur, *bsum, *esrc;
    cudaGetSymbolAddress((void**)&dinv, g_dinv);
    cudaGetSymbolAddress((void**)&H,    g_h);
    cudaGetSymbolAddress((void**)&AGG,  g_agg);
    cudaGetSymbolAddress((void**)&cnt,  g_cnt);
    cudaGetSymbolAddress((void**)&incl, g_incl);
    cudaGetSymbolAddress((void**)&off,  g_off);
    cudaGetSymbolAddress((void**)&cur,  g_cur);
    cudaGetSymbolAddress((void**)&bsum, g_bsum);
    cudaGetSymbolAddress((void**)&esrc, g_esrc);

    float* out = (float*)d_out;

    int nb1024 = (M + 1023) / 1024;

    // dtype + CSR build
    k_detect<<<1, 256>>>((const int*)ei, 2 * E);
    k_zero_cnt<<<(M + 255) / 256, 256>>>(cnt, M);
    k_hist<<<(E + 255) / 256, 256>>>(ei, cnt, E, M);
    k_dinv<<<(M + 255) / 256, 256>>>(cnt, dinv, M);
    k_scan1<<<nb1024, 1024>>>(cnt, incl, bsum, M);
    k_scan2<<<1, 32>>>(bsum, nb1024);
    k_scan3<<<(M + 255) / 256, 256>>>(incl, cnt, bsum, off, cur, M);
    k_fill<<<(E + 255) / 256, 256>>>(ei, cur, esrc, E, M);

    int gblocks = (M + 127) / 128;
    int ablocks = (M * 32 + 255) / 256;   // 1 warp/node, 8 warps/block

    // layer 1: x@w1 -> H; aggregate + b1 + relu -> AGG (= hidden)
    k_gemm1<<<gblocks, 256>>>(x, w1, H, M);
    k_agg<true><<<ablocks, 256>>>(esrc, off, cnt, dinv, b1, H, AGG, M);
    // layer 2 shared aggregation: AGG (hidden) -> H (= agg2)
    k_agg<false><<<ablocks, 256>>>(esrc, off, cnt, dinv, nullptr, AGG, H, M);
    // fused output GEMM
    k_gemm2<<<gblocks, 256>>>(H, w2, w3, b2, b3, out, M);
    (void)out_size;
}

// round 5
// speedup vs baseline: 2.0368x; 1.3166x over previous
#include <cuda_runtime.h>
#include <cuda_bf16.h>
#include <cstdint>

#define F_IN 256
#define H1   128
#define H2   64
#define MAXN 100000
#define MAXE 2000000

// Scratch (__device__ globals; allocation-free rule)
__device__ __align__(256) float g_dinv[MAXN];
__device__ __align__(256) float g_h[(size_t)MAXN * H1];    // h1, later agg2
__device__ __align__(256) float g_agg[(size_t)MAXN * H1];  // hidden
__device__ int g_cnt[MAXN];
__device__ int g_incl[MAXN];
__device__ int g_off[MAXN];
__device__ int g_cur[MAXN];
__device__ int g_bsum[256];
__device__ int g_esrc[MAXE];
__device__ int g_is64;

// ---------------------------------------------------------------------------
__global__ void k_detect(const int* __restrict__ ei32, int words) {
    __shared__ int anynz;
    if (threadIdx.x == 0) anynz = 0;
    __syncthreads();
    int idx = 1 + 2 * (int)threadIdx.x;
    if (idx < words && ei32[idx] != 0) atomicExch(&anynz, 1);
    __syncthreads();
    if (threadIdx.x == 0) g_is64 = (anynz == 0) ? 1 : 0;
}

__device__ __forceinline__ int edge_at(const void* ei, size_t idx) {
    if (g_is64) return (int)((const long long*)ei)[idx];
    return ((const int*)ei)[idx];
}

__global__ void k_zero_cnt(int* cnt, int n) {
    int i = blockIdx.x * blockDim.x + threadIdx.x;
    if (i < n) cnt[i] = 0;
}

__global__ void k_hist(const void* __restrict__ ei, int* cnt, int E, int M) {
    int e = blockIdx.x * blockDim.x + threadIdx.x;
    if (e < E) {
        int d = edge_at(ei, (size_t)E + e);
        if ((unsigned)d < (unsigned)M) atomicAdd(cnt + d, 1);
    }
}

__global__ void k_dinv(const int* __restrict__ cnt, float* dinv, int n) {
    int i = blockIdx.x * blockDim.x + threadIdx.x;
    if (i < n) dinv[i] = rsqrtf(1.0f + (float)cnt[i]);
}

__global__ void k_scan1(const int* __restrict__ cnt, int* incl, int* bsum, int M) {
    __shared__ int sh[1024];
    int i = blockIdx.x * 1024 + threadIdx.x;
    int v = (i < M) ? cnt[i] : 0;
    sh[threadIdx.x] = v;
    __syncthreads();
#pragma unroll
    for (int d = 1; d < 1024; d <<= 1) {
        int t = (threadIdx.x >= d) ? sh[threadIdx.x - d] : 0;
        __syncthreads();
        sh[threadIdx.x] += t;
        __syncthreads();
    }
    if (i < M) incl[i] = sh[threadIdx.x];
    if (threadIdx.x == 1023) bsum[blockIdx.x] = sh[1023];
}

// Parallel block-sum exclusive scan (nb <= 128)
__global__ void k_scan2(int* bsum, int nb) {
    __shared__ int sh[128];
    int t = threadIdx.x;
    int v = (t < nb) ? bsum[t] : 0;
    sh[t] = v;
    __syncthreads();
#pragma unroll
    for (int d = 1; d < 128; d <<= 1) {
        int x = (t >= d) ? sh[t - d] : 0;
        __syncthreads();
        sh[t] += x;
        __syncthreads();
    }
    if (t < nb) bsum[t] = sh[t] - v;
}

__global__ void k_scan3(const int* __restrict__ incl, const int* __restrict__ cnt,
                        const int* __restrict__ bsum, int* off, int* cur, int M) {
    int i = blockIdx.x * blockDim.x + threadIdx.x;
    if (i < M) {
        int o = incl[i] - cnt[i] + bsum[i >> 10];
        off[i] = o;
        cur[i] = o;
    }
}

__global__ void k_fill(const void* __restrict__ ei, int* cur, int* esrc, int E, int M) {
    int e = blockIdx.x * blockDim.x + threadIdx.x;
    if (e < E) {
        int s = edge_at(ei, (size_t)e);
        int d = edge_at(ei, (size_t)E + e);
        if ((unsigned)s < (unsigned)M && (unsigned)d < (unsigned)M) {
            int pos = atomicAdd(cur + d, 1);
            esrc[pos] = s;
        }
    }
}

// ---------------------------------------------------------------------------
// TF32 tensor-core GEMM. C[M,128] = A[M,KT] @ B[KT,128] (+epilogue).
// BM=128, BN=128, KCHUNK=16, 256 threads (8 warps as 4m x 2n, warp tile 32x64).
// SPLIT=false: plain store to out[M,128].
// SPLIT=true : B = [B1|B2] (each KTx64), bias added, mu/logvar split store.
__device__ __forceinline__ uint32_t f2tf32(float f) {
    uint32_t u;
    asm("cvt.rna.tf32.f32 %0, %1;" : "=r"(u) : "f"(f));
    return u;
}

__device__ __forceinline__ void mma_tf32(float* c, const uint32_t* a,
                                         uint32_t b0, uint32_t b1) {
    asm volatile(
        "mma.sync.aligned.m16n8k8.row.col.f32.tf32.tf32.f32 "
        "{%0,%1,%2,%3}, {%4,%5,%6,%7}, {%8,%9}, {%0,%1,%2,%3};\n"
        : "+f"(c[0]), "+f"(c[1]), "+f"(c[2]), "+f"(c[3])
        : "r"(a[0]), "r"(a[1]), "r"(a[2]), "r"(a[3]), "r"(b0), "r"(b1));
}

template<int KT, bool SPLIT>
__global__ __launch_bounds__(256) void k_gemm_tc(
    const float* __restrict__ A,
    const float* __restrict__ B1, const float* __restrict__ B2,
    const float* __restrict__ bias1, const float* __restrict__ bias2,
    float* __restrict__ out, int M)
{
    __shared__ uint32_t As[2][128][20];   // [row][k] stride 20 -> conflict-free frags
    __shared__ uint32_t BsT[2][128][20];  // [col][k]

    const int tid = threadIdx.x;
    const int lane = tid & 31;
    const int quad = lane >> 2;
    const int kq = lane & 3;
    const int warp = tid >> 5;
    const int wm = warp & 3;      // 4 m-warps
    const int wn = warp >> 2;     // 2 n-warps
    const int brow = blockIdx.x * 128;

    float c[2][8][4];
#pragma unroll
    for (int mt = 0; mt < 2; mt++)
#pragma unroll
        for (int nt = 0; nt < 8; nt++)
#pragma unroll
            for (int i = 0; i < 4; i++) c[mt][nt][i] = 0.0f;

    float4 ra[2], rb[2];

    auto loadG = [&](int k0) {
#pragma unroll
        for (int t = 0; t < 2; t++) {
            int idx = tid + t * 256;
            int row = idx >> 2, kk0 = (idx & 3) * 4;
            int gr = brow + row;
            ra[t] = (gr < M) ? *(const float4*)(A + (size_t)gr * KT + k0 + kk0)
                             : make_float4(0.f, 0.f, 0.f, 0.f);
        }
#pragma unroll
        for (int t = 0; t < 2; t++) {
            int idx = tid + t * 256;
            int k = idx >> 5, c0 = (idx & 31) * 4;
            if (!SPLIT)
                rb[t] = *(const float4*)(B1 + (size_t)(k0 + k) * 128 + c0);
            else if (c0 < 64)
                rb[t] = *(const float4*)(B1 + (size_t)(k0 + k) * 64 + c0);
            else
                rb[t] = *(const float4*)(B2 + (size_t)(k0 + k) * 64 + (c0 - 64));
        }
    };

    auto stage = [&](int buf) {
#pragma unroll
        for (int t = 0; t < 2; t++) {
            int idx = tid + t * 256;
            int row = idx >> 2, kk0 = (idx & 3) * 4;
            uint4 u = make_uint4(f2tf32(ra[t].x), f2tf32(ra[t].y),
                                 f2tf32(ra[t].z), f2tf32(ra[t].w));
            *(uint4*)&As[buf][row][kk0] = u;
        }
#pragma unroll
        for (int t = 0; t < 2; t++) {
            int idx = tid + t * 256;
            int k = idx >> 5, c0 = (idx & 31) * 4;
            BsT[buf][c0 + 0][k] = f2tf32(rb[t].x);
            BsT[buf][c0 + 1][k] = f2tf32(rb[t].y);
            BsT[buf][c0 + 2][k] = f2tf32(rb[t].z);
            BsT[buf][c0 + 3][k] = f2tf32(rb[t].w);
        }
    };

    const int NC = KT / 16;
    loadG(0);
    stage(0);
    __syncthreads();

    for (int ch = 0; ch < NC; ch++) {
        int buf = ch & 1;
        if (ch + 1 < NC) loadG((ch + 1) * 16);
#pragma unroll
        for (int ks = 0; ks < 2; ks++) {
            uint32_t a[2][4];
#pragma unroll
            for (int mt = 0; mt < 2; mt++) {
                int r = wm * 32 + mt * 16 + quad;
                a[mt][0] = As[buf][r][ks * 8 + kq];
                a[mt][1] = As[buf][r + 8][ks * 8 + kq];
                a[mt][2] = As[buf][r][ks * 8 + kq + 4];
                a[mt][3] = As[buf][r + 8][ks * 8 + kq + 4];
            }
#pragma unroll
            for (int nt = 0; nt < 8; nt++) {
                int cb = wn * 64 + nt * 8 + quad;
                uint32_t b0 = BsT[buf][cb][ks * 8 + kq];
                uint32_t b1 = BsT[buf][cb][ks * 8 + kq + 4];
                mma_tf32(c[0][nt], a[0], b0, b1);
                mma_tf32(c[1][nt], a[1], b0, b1);
            }
        }
        if (ch + 1 < NC) stage(buf ^ 1);
        __syncthreads();
    }

    // epilogue
#pragma unroll
    for (int mt = 0; mt < 2; mt++) {
#pragma unroll
        for (int nt = 0; nt < 8; nt++) {
            int r0 = brow + wm * 32 + mt * 16 + quad;
            int col = wn * 64 + nt * 8 + kq * 2;
            float2 lo = make_float2(c[mt][nt][0], c[mt][nt][1]);
            float2 hi = make_float2(c[mt][nt][2], c[mt][nt][3]);
            if (!SPLIT) {
                if (r0 < M)     *(float2*)(out + (size_t)r0 * 128 + col) = lo;
                if (r0 + 8 < M) *(float2*)(out + (size_t)(r0 + 8) * 128 + col) = hi;
            } else {
                const float* bs = wn ? bias2 : bias1;
                int chn = col - wn * 64;
                float bx = bs[chn], by = bs[chn + 1];
                size_t base = wn ? (size_t)M * 64 : 0;
                lo.x += bx; lo.y += by; hi.x += bx; hi.y += by;
                if (r0 < M)     *(float2*)(out + base + (size_t)r0 * 64 + chn) = lo;
                if (r0 + 8 < M) *(float2*)(out + base + (size_t)(r0 + 8) * 64 + chn) = hi;
            }
        }
    }
}

// ---------------------------------------------------------------------------
// CSR aggregation: one warp per dst node (unchanged from R4 — near L2 bound)
template<bool RELU>
__global__ __launch_bounds__(256) void k_agg(
    const int* __restrict__ esrc, const int* __restrict__ off,
    const int* __restrict__ cnt, const float* __restrict__ dinv,
    const float* __restrict__ bias,
    const float* __restrict__ Hin, float* __restrict__ Hout, int M)
{
    int node = (blockIdx.x * blockDim.x + threadIdx.x) >> 5;
    int lane = threadIdx.x & 31;
    if (node >= M) return;
    float di = dinv[node];
    float d2 = di * di;
    float4 acc = *(const float4*)(Hin + (size_t)node * 128 + lane * 4);
    acc.x *= d2; acc.y *= d2; acc.z *= d2; acc.w *= d2;

    int o = off[node], c = cnt[node];
    for (int base = 0; base < c; base += 32) {
        int rem = c - base;
        int lim = rem < 32 ? rem : 32;
        int sv = 0; float dv = 0.f;
        if (lane < lim) { sv = esrc[o + base + lane]; dv = dinv[sv]; }
        for (int j = 0; j < lim; j++) {
            int s = __shfl_sync(0xffffffffu, sv, j);
            float ds = __shfl_sync(0xffffffffu, dv, j);
            float coef = ds * di;
            float4 v = *(const float4*)(Hin + (size_t)s * 128 + lane * 4);
            acc.x = fmaf(v.x, coef, acc.x);
            acc.y = fmaf(v.y, coef, acc.y);
            acc.z = fmaf(v.z, coef, acc.z);
            acc.w = fmaf(v.w, coef, acc.w);
        }
    }
    if (RELU) {
        float4 b4 = *(const float4*)(bias + lane * 4);
        acc.x = fmaxf(acc.x + b4.x, 0.f);
        acc.y = fmaxf(acc.y + b4.y, 0.f);
        acc.z = fmaxf(acc.z + b4.z, 0.f);
        acc.w = fmaxf(acc.w + b4.w, 0.f);
    }
    *(float4*)(Hout + (size_t)node * 128 + lane * 4) = acc;
}

// ---------------------------------------------------------------------------
extern "C" void kernel_launch(void* const* d_in, const int* in_sizes, int n_in,
                              void* d_out, int out_size)
{
    const float *x = nullptr, *w1 = nullptr, *b1 = nullptr;
    const float *w2 = nullptr, *b2 = nullptr, *w3 = nullptr, *b3 = nullptr;
    const void* ei = nullptr;
    int M = 0, E = 0;

    for (int i = 0; i < n_in; i++) {
        int sz = in_sizes[i];
        if (sz == F_IN * H1) {
            w1 = (const float*)d_in[i];
        } else if (sz == H1) {
            b1 = (const float*)d_in[i];
        } else if (sz == H1 * H2) {
            if (!w2) w2 = (const float*)d_in[i];
            else     w3 = (const float*)d_in[i];
        } else if (sz == H2) {
            if (!b2) b2 = (const float*)d_in[i];
            else     b3 = (const float*)d_in[i];
        } else if (sz < 8000000) {
            ei = d_in[i];
            E = sz / 2;
        } else {
            x = (const float*)d_in[i];
            M = sz / F_IN;
        }
    }

    float *dinv, *H, *AGG;
    int *cnt, *incl, *off, *cur, *bsum, *esrc;
    cudaGetSymbolAddress((void**)&dinv, g_dinv);
    cudaGetSymbolAddress((void**)&H,    g_h);
    cudaGetSymbolAddress((void**)&AGG,  g_agg);
    cudaGetSymbolAddress((void**)&cnt,  g_cnt);
    cudaGetSymbolAddress((void**)&incl, g_incl);
    cudaGetSymbolAddress((void**)&off,  g_off);
    cudaGetSymbolAddress((void**)&cur,  g_cur);
    cudaGetSymbolAddress((void**)&bsum, g_bsum);
    cudaGetSymbolAddress((void**)&esrc, g_esrc);

    float* out = (float*)d_out;

    int nb1024 = (M + 1023) / 1024;

    k_detect<<<1, 256>>>((const int*)ei, 2 * E);
    k_zero_cnt<<<(M + 255) / 256, 256>>>(cnt, M);
    k_hist<<<(E + 255) / 256, 256>>>(ei, cnt, E, M);
    k_dinv<<<(M + 255) / 256, 256>>>(cnt, dinv, M);
    k_scan1<<<nb1024, 1024>>>(cnt, incl, bsum, M);
    k_scan2<<<1, 128>>>(bsum, nb1024);
    k_scan3<<<(M + 255) / 256, 256>>>(incl, cnt, bsum, off, cur, M);
    k_fill<<<(E + 255) / 256, 256>>>(ei, cur, esrc, E, M);

    int gblocks = (M + 127) / 128;
    int ablocks = (M * 32 + 255) / 256;

    // layer 1: x@w1 -> H (tensor cores); aggregate + b1 + relu -> AGG
    k_gemm_tc<F_IN, false><<<gblocks, 256>>>(x, w1, nullptr, nullptr, nullptr, H, M);
    k_agg<true><<<ablocks, 256>>>(esrc, off, cnt, dinv, b1, H, AGG, M);
    // layer 2 shared aggregation: AGG (hidden) -> H (= agg2)
    k_agg<false><<<ablocks, 256>>>(esrc, off, cnt, dinv, nullptr, AGG, H, M);
    // fused output GEMM: H @ [w2|w3] + [b2|b3] -> (mu, logvar)
    k_gemm_tc<H1, true><<<gblocks, 256>>>(H, w2, w3, b2, b3, out, M);
    (void)out_size;
}

// round 6
// speedup vs baseline: 2.2979x; 1.1282x over previous
#include <cuda_runtime.h>
#include <cuda_fp16.h>
#include <cstdint>

#define F_IN 256
#define H1   128
#define H2   64
#define MAXN 100000
#define MAXE 2000000

// Scratch (__device__ globals; allocation-free rule)
__device__ __align__(256) float g_dinv[MAXN];
__device__ __align__(256) float g_h[(size_t)MAXN * H1];    // h1(fp16) -> agg2(fp32)
__device__ __align__(256) float g_agg[(size_t)MAXN * H1];  // hidden(fp16)
__device__ int g_cnt[MAXN];
__device__ int g_incl[MAXN];
__device__ int g_off[MAXN];
__device__ int g_cur[MAXN];
__device__ int g_bsum[256];
__device__ int g_esrc[MAXE];
__device__ int g_is64;

// ---------------------------------------------------------------------------
__global__ void k_detect(const int* __restrict__ ei32, int words) {
    __shared__ int anynz;
    if (threadIdx.x == 0) anynz = 0;
    __syncthreads();
    int idx = 1 + 2 * (int)threadIdx.x;
    if (idx < words && ei32[idx] != 0) atomicExch(&anynz, 1);
    __syncthreads();
    if (threadIdx.x == 0) g_is64 = (anynz == 0) ? 1 : 0;
}

__device__ __forceinline__ int edge_at(const void* ei, size_t idx) {
    if (g_is64) return (int)((const long long*)ei)[idx];
    return ((const int*)ei)[idx];
}

__global__ void k_zero_cnt(int* cnt, int n) {
    int i = blockIdx.x * blockDim.x + threadIdx.x;
    if (i < n) cnt[i] = 0;
}

__global__ void k_hist(const void* __restrict__ ei, int* cnt, int E, int M) {
    int e = blockIdx.x * blockDim.x + threadIdx.x;
    if (e < E) {
        int d = edge_at(ei, (size_t)E + e);
        if ((unsigned)d < (unsigned)M) atomicAdd(cnt + d, 1);
    }
}

__global__ void k_dinv(const int* __restrict__ cnt, float* dinv, int n) {
    int i = blockIdx.x * blockDim.x + threadIdx.x;
    if (i < n) dinv[i] = rsqrtf(1.0f + (float)cnt[i]);
}

__global__ void k_scan1(const int* __restrict__ cnt, int* incl, int* bsum, int M) {
    __shared__ int sh[1024];
    int i = blockIdx.x * 1024 + threadIdx.x;
    int v = (i < M) ? cnt[i] : 0;
    sh[threadIdx.x] = v;
    __syncthreads();
#pragma unroll
    for (int d = 1; d < 1024; d <<= 1) {
        int t = (threadIdx.x >= d) ? sh[threadIdx.x - d] : 0;
        __syncthreads();
        sh[threadIdx.x] += t;
        __syncthreads();
    }
    if (i < M) incl[i] = sh[threadIdx.x];
    if (threadIdx.x == 1023) bsum[blockIdx.x] = sh[1023];
}

__global__ void k_scan2(int* bsum, int nb) {
    __shared__ int sh[128];
    int t = threadIdx.x;
    int v = (t < nb) ? bsum[t] : 0;
    sh[t] = v;
    __syncthreads();
#pragma unroll
    for (int d = 1; d < 128; d <<= 1) {
        int x = (t >= d) ? sh[t - d] : 0;
        __syncthreads();
        sh[t] += x;
        __syncthreads();
    }
    if (t < nb) bsum[t] = sh[t] - v;
}

__global__ void k_scan3(const int* __restrict__ incl, const int* __restrict__ cnt,
                        const int* __restrict__ bsum, int* off, int* cur, int M) {
    int i = blockIdx.x * blockDim.x + threadIdx.x;
    if (i < M) {
        int o = incl[i] - cnt[i] + bsum[i >> 10];
        off[i] = o;
        cur[i] = o;
    }
}

__global__ void k_fill(const void* __restrict__ ei, int* cur, int* esrc, int E, int M) {
    int e = blockIdx.x * blockDim.x + threadIdx.x;
    if (e < E) {
        int s = edge_at(ei, (size_t)e);
        int d = edge_at(ei, (size_t)E + e);
        if ((unsigned)s < (unsigned)M && (unsigned)d < (unsigned)M) {
            int pos = atomicAdd(cur + d, 1);
            esrc[pos] = s;
        }
    }
}

// ---------------------------------------------------------------------------
// TF32 tensor-core GEMM. BM=128, BN=128, KCHUNK=16, 256 threads.
// OUTHALF: store fp16 rows [M][128]. SPLIT: [B1|B2] + bias, mu/logvar split.
__device__ __forceinline__ uint32_t f2tf32(float f) {
    uint32_t u;
    asm("cvt.rna.tf32.f32 %0, %1;" : "=r"(u) : "f"(f));
    return u;
}

__device__ __forceinline__ void mma_tf32(float* c, const uint32_t* a,
                                         uint32_t b0, uint32_t b1) {
    asm volatile(
        "mma.sync.aligned.m16n8k8.row.col.f32.tf32.tf32.f32 "
        "{%0,%1,%2,%3}, {%4,%5,%6,%7}, {%8,%9}, {%0,%1,%2,%3};\n"
        : "+f"(c[0]), "+f"(c[1]), "+f"(c[2]), "+f"(c[3])
        : "r"(a[0]), "r"(a[1]), "r"(a[2]), "r"(a[3]), "r"(b0), "r"(b1));
}

template<int KT, bool SPLIT, bool OUTHALF>
__global__ __launch_bounds__(256) void k_gemm_tc(
    const float* __restrict__ A,
    const float* __restrict__ B1, const float* __restrict__ B2,
    const float* __restrict__ bias1, const float* __restrict__ bias2,
    void* __restrict__ outv, int M)
{
    __shared__ uint32_t As[2][128][20];
    __shared__ uint32_t BsT[2][128][20];

    const int tid = threadIdx.x;
    const int lane = tid & 31;
    const int quad = lane >> 2;
    const int kq = lane & 3;
    const int warp = tid >> 5;
    const int wm = warp & 3;
    const int wn = warp >> 2;
    const int brow = blockIdx.x * 128;

    float c[2][8][4];
#pragma unroll
    for (int mt = 0; mt < 2; mt++)
#pragma unroll
        for (int nt = 0; nt < 8; nt++)
#pragma unroll
            for (int i = 0; i < 4; i++) c[mt][nt][i] = 0.0f;

    float4 ra[2], rb[2];

    auto loadG = [&](int k0) {
#pragma unroll
        for (int t = 0; t < 2; t++) {
            int idx = tid + t * 256;
            int row = idx >> 2, kk0 = (idx & 3) * 4;
            int gr = brow + row;
            ra[t] = (gr < M) ? *(const float4*)(A + (size_t)gr * KT + k0 + kk0)
                             : make_float4(0.f, 0.f, 0.f, 0.f);
        }
#pragma unroll
        for (int t = 0; t < 2; t++) {
            int idx = tid + t * 256;
            int k = idx >> 5, c0 = (idx & 31) * 4;
            if (!SPLIT)
                rb[t] = *(const float4*)(B1 + (size_t)(k0 + k) * 128 + c0);
            else if (c0 < 64)
                rb[t] = *(const float4*)(B1 + (size_t)(k0 + k) * 64 + c0);
            else
                rb[t] = *(const float4*)(B2 + (size_t)(k0 + k) * 64 + (c0 - 64));
        }
    };

    auto stage = [&](int buf) {
#pragma unroll
        for (int t = 0; t < 2; t++) {
            int idx = tid + t * 256;
            int row = idx >> 2, kk0 = (idx & 3) * 4;
            uint4 u = make_uint4(f2tf32(ra[t].x), f2tf32(ra[t].y),
                                 f2tf32(ra[t].z), f2tf32(ra[t].w));
            *(uint4*)&As[buf][row][kk0] = u;
        }
#pragma unroll
        for (int t = 0; t < 2; t++) {
            int idx = tid + t * 256;
            int k = idx >> 5, c0 = (idx & 31) * 4;
            BsT[buf][c0 + 0][k] = f2tf32(rb[t].x);
            BsT[buf][c0 + 1][k] = f2tf32(rb[t].y);
            BsT[buf][c0 + 2][k] = f2tf32(rb[t].z);
            BsT[buf][c0 + 3][k] = f2tf32(rb[t].w);
        }
    };

    const int NC = KT / 16;
    loadG(0);
    stage(0);
    __syncthreads();

    for (int ch = 0; ch < NC; ch++) {
        int buf = ch & 1;
        if (ch + 1 < NC) loadG((ch + 1) * 16);
#pragma unroll
        for (int ks = 0; ks < 2; ks++) {
            uint32_t a[2][4];
#pragma unroll
            for (int mt = 0; mt < 2; mt++) {
                int r = wm * 32 + mt * 16 + quad;
                a[mt][0] = As[buf][r][ks * 8 + kq];
                a[mt][1] = As[buf][r + 8][ks * 8 + kq];
                a[mt][2] = As[buf][r][ks * 8 + kq + 4];
                a[mt][3] = As[buf][r + 8][ks * 8 + kq + 4];
            }
#pragma unroll
            for (int nt = 0; nt < 8; nt++) {
                int cb = wn * 64 + nt * 8 + quad;
                uint32_t b0 = BsT[buf][cb][ks * 8 + kq];
                uint32_t b1 = BsT[buf][cb][ks * 8 + kq + 4];
                mma_tf32(c[0][nt], a[0], b0, b1);
                mma_tf32(c[1][nt], a[1], b0, b1);
            }
        }
        if (ch + 1 < NC) stage(buf ^ 1);
        __syncthreads();
    }

#pragma unroll
    for (int mt = 0; mt < 2; mt++) {
#pragma unroll
        for (int nt = 0; nt < 8; nt++) {
            int r0 = brow + wm * 32 + mt * 16 + quad;
            int col = wn * 64 + nt * 8 + kq * 2;
            float2 lo = make_float2(c[mt][nt][0], c[mt][nt][1]);
            float2 hi = make_float2(c[mt][nt][2], c[mt][nt][3]);
            if (OUTHALF) {
                __half* out16 = (__half*)outv;
                if (r0 < M)
                    *(__half2*)(out16 + (size_t)r0 * 128 + col) = __float22half2_rn(lo);
                if (r0 + 8 < M)
                    *(__half2*)(out16 + (size_t)(r0 + 8) * 128 + col) = __float22half2_rn(hi);
            } else if (!SPLIT) {
                float* out = (float*)outv;
                if (r0 < M)     *(float2*)(out + (size_t)r0 * 128 + col) = lo;
                if (r0 + 8 < M) *(float2*)(out + (size_t)(r0 + 8) * 128 + col) = hi;
            } else {
                float* out = (float*)outv;
                const float* bs = wn ? bias2 : bias1;
                int chn = col - wn * 64;
                float bx = bs[chn], by = bs[chn + 1];
                size_t base = wn ? (size_t)M * 64 : 0;
                lo.x += bx; lo.y += by; hi.x += bx; hi.y += by;
                if (r0 < M)     *(float2*)(out + base + (size_t)r0 * 64 + chn) = lo;
                if (r0 + 8 < M) *(float2*)(out + base + (size_t)(r0 + 8) * 64 + chn) = hi;
            }
        }
    }
}

// ---------------------------------------------------------------------------
// CSR aggregation over fp16 features. One warp per dst node; 4 halves/lane.
// OUT_HALF: write fp16 (hidden); else write fp32 (GEMM2 input).
template<bool RELU, bool OUT_HALF>
__global__ __launch_bounds__(256) void k_agg(
    const int* __restrict__ esrc, const int* __restrict__ off,
    const int* __restrict__ cnt, const float* __restrict__ dinv,
    const float* __restrict__ bias,
    const __half* __restrict__ Hin, void* __restrict__ Houtv, int M)
{
    int node = (blockIdx.x * blockDim.x + threadIdx.x) >> 5;
    int lane = threadIdx.x & 31;
    if (node >= M) return;
    float di = dinv[node];
    float d2 = di * di;

    uint2 raw = *(const uint2*)(Hin + (size_t)node * 128 + lane * 4);
    float2 f0 = __half22float2(*(__half2*)&raw.x);
    float2 f1 = __half22float2(*(__half2*)&raw.y);
    float a0 = f0.x * d2, a1 = f0.y * d2, a2 = f1.x * d2, a3 = f1.y * d2;

    int o = off[node], c = cnt[node];
    for (int base = 0; base < c; base += 32) {
        int rem = c - base;
        int lim = rem < 32 ? rem : 32;
        int sv = 0; float dv = 0.f;
        if (lane < lim) { sv = esrc[o + base + lane]; dv = dinv[sv]; }
        for (int j = 0; j < lim; j++) {
            int s = __shfl_sync(0xffffffffu, sv, j);
            float ds = __shfl_sync(0xffffffffu, dv, j);
            float coef = ds * di;
            uint2 r = *(const uint2*)(Hin + (size_t)s * 128 + lane * 4);
            float2 v0 = __half22float2(*(__half2*)&r.x);
            float2 v1 = __half22float2(*(__half2*)&r.y);
            a0 = fmaf(v0.x, coef, a0);
            a1 = fmaf(v0.y, coef, a1);
            a2 = fmaf(v1.x, coef, a2);
            a3 = fmaf(v1.y, coef, a3);
        }
    }
    if (RELU) {
        float4 b4 = *(const float4*)(bias + lane * 4);
        a0 = fmaxf(a0 + b4.x, 0.f);
        a1 = fmaxf(a1 + b4.y, 0.f);
        a2 = fmaxf(a2 + b4.z, 0.f);
        a3 = fmaxf(a3 + b4.w, 0.f);
    }
    if (OUT_HALF) {
        __half* out16 = (__half*)Houtv;
        uint2 w;
        *(__half2*)&w.x = __float22half2_rn(make_float2(a0, a1));
        *(__half2*)&w.y = __float22half2_rn(make_float2(a2, a3));
        *(uint2*)(out16 + (size_t)node * 128 + lane * 4) = w;
    } else {
        float* out = (float*)Houtv;
        *(float4*)(out + (size_t)node * 128 + lane * 4) = make_float4(a0, a1, a2, a3);
    }
}

// ---------------------------------------------------------------------------
extern "C" void kernel_launch(void* const* d_in, const int* in_sizes, int n_in,
                              void* d_out, int out_size)
{
    const float *x = nullptr, *w1 = nullptr, *b1 = nullptr;
    const float *w2 = nullptr, *b2 = nullptr, *w3 = nullptr, *b3 = nullptr;
    const void* ei = nullptr;
    int M = 0, E = 0;

    for (int i = 0; i < n_in; i++) {
        int sz = in_sizes[i];
        if (sz == F_IN * H1) {
            w1 = (const float*)d_in[i];
        } else if (sz == H1) {
            b1 = (const float*)d_in[i];
        } else if (sz == H1 * H2) {
            if (!w2) w2 = (const float*)d_in[i];
            else     w3 = (const float*)d_in[i];
        } else if (sz == H2) {
            if (!b2) b2 = (const float*)d_in[i];
            else     b3 = (const float*)d_in[i];
        } else if (sz < 8000000) {
            ei = d_in[i];
            E = sz / 2;
        } else {
            x = (const float*)d_in[i];
            M = sz / F_IN;
        }
    }

    float *dinv, *H, *AGG;
    int *cnt, *incl, *off, *cur, *bsum, *esrc;
    cudaGetSymbolAddress((void**)&dinv, g_dinv);
    cudaGetSymbolAddress((void**)&H,    g_h);
    cudaGetSymbolAddress((void**)&AGG,  g_agg);
    cudaGetSymbolAddress((void**)&cnt,  g_cnt);
    cudaGetSymbolAddress((void**)&incl, g_incl);
    cudaGetSymbolAddress((void**)&off,  g_off);
    cudaGetSymbolAddress((void**)&cur,  g_cur);
    cudaGetSymbolAddress((void**)&bsum, g_bsum);
    cudaGetSymbolAddress((void**)&esrc, g_esrc);

    float* out = (float*)d_out;
    __half* H16   = (__half*)H;     // h1 in fp16 (g_h)
    __half* HID16 = (__half*)AGG;   // hidden in fp16 (g_agg)

    int nb1024 = (M + 1023) / 1024;

    k_detect<<<1, 256>>>((const int*)ei, 2 * E);
    k_zero_cnt<<<(M + 255) / 256, 256>>>(cnt, M);
    k_hist<<<(E + 255) / 256, 256>>>(ei, cnt, E, M);
    k_dinv<<<(M + 255) / 256, 256>>>(cnt, dinv, M);
    k_scan1<<<nb1024, 1024>>>(cnt, incl, bsum, M);
    k_scan2<<<1, 128>>>(bsum, nb1024);
    k_scan3<<<(M + 255) / 256, 256>>>(incl, cnt, bsum, off, cur, M);
    k_fill<<<(E + 255) / 256, 256>>>(ei, cur, esrc, E, M);

    int gblocks = (M + 127) / 128;
    int ablocks = (M * 32 + 255) / 256;

    // layer 1: x@w1 -> H16 (fp16); agg + b1 + relu -> HID16 (fp16)
    k_gemm_tc<F_IN, false, true><<<gblocks, 256>>>(x, w1, nullptr, nullptr, nullptr, H16, M);
    k_agg<true, true><<<ablocks, 256>>>(esrc, off, cnt, dinv, b1, H16, HID16, M);
    // layer 2 aggregation: HID16 -> H (fp32, GEMM2 input)
    k_agg<false, false><<<ablocks, 256>>>(esrc, off, cnt, dinv, nullptr, HID16, H, M);
    // fused output GEMM: H @ [w2|w3] + [b2|b3] -> (mu, logvar)
    k_gemm_tc<H1, true, false><<<gblocks, 256>>>(H, w2, w3, b2, b3, out, M);
    (void)out_size;
}